// round 1
// baseline (speedup 1.0000x reference)
#include <cuda_runtime.h>
#include <stdint.h>

#define NB   64
#define NC   768
#define NN   576
#define NG   3
#define GS   192
#define NIMG 2

// Scratch (device globals — no allocation allowed)
__device__ float         g_heat   [NIMG * NB * NN];          // channel-sums per position
__device__ unsigned char g_label  [NIMG * NB * NN];          // tercile id per position
__device__ float         g_gsum   [NIMG * NB * NG * NC];     // group sums [img][b][g][c]
__device__ float         g_partial[NB];                      // per-b sum of squared diffs

// ---------------------------------------------------------------------------
// Kernel A: heat[img][b][n] = sum_c in[b][c][n]   (ordering == mean ordering)
// One thread per (img,b,n). Consecutive threads -> consecutive n -> coalesced.
// ---------------------------------------------------------------------------
__global__ void heat_kernel(const float* __restrict__ in0,
                            const float* __restrict__ in1) {
    int idx = blockIdx.x * blockDim.x + threadIdx.x;   // 0 .. 2*64*576-1
    int n = idx % NN;
    int t = idx / NN;                                  // img*NB + b
    int b = t % NB;
    const float* src = (t >= NB) ? in1 : in0;
    const float* p = src + (size_t)b * NC * NN + n;
    float s0 = 0.f, s1 = 0.f, s2 = 0.f, s3 = 0.f;
#pragma unroll 4
    for (int c = 0; c < NC; c += 4) {
        s0 += p[(size_t)(c + 0) * NN];
        s1 += p[(size_t)(c + 1) * NN];
        s2 += p[(size_t)(c + 2) * NN];
        s3 += p[(size_t)(c + 3) * NN];
    }
    g_heat[idx] = (s0 + s1) + (s2 + s3);
}

// ---------------------------------------------------------------------------
// Kernel B: per (img,b), rank every position by descending heat (stable by
// index, matching jnp.argsort(-h)) and label with its tercile.
// ---------------------------------------------------------------------------
__global__ void label_kernel() {
    __shared__ float sh[NN];
    int base = blockIdx.x * NN;        // blockIdx.x = img*NB + b
    int tid = threadIdx.x;             // 0..575
    sh[tid] = g_heat[base + tid];
    __syncthreads();
    float h = sh[tid];
    int r = 0;
#pragma unroll 8
    for (int m = 0; m < NN; ++m) {
        float hm = sh[m];
        r += (hm > h) || (hm == h && m < tid);
    }
    int g = r / GS;                    // 0,1,2
    g_label[base + tid] = (unsigned char)g;
}

// ---------------------------------------------------------------------------
// Kernel C: gsum[img][b][g][c] = sum over n with label g of in[b][c][n].
// One warp per (img,b,c); lanes stride the contiguous row (coalesced).
// Block index reversed so this pass starts on the data kernel A read last
// (L2 reuse).
// ---------------------------------------------------------------------------
__global__ void gsum_kernel(const float* __restrict__ in0,
                            const float* __restrict__ in1) {
    __shared__ unsigned char slab[NN];
    int flat = gridDim.x - 1 - blockIdx.x;   // reversed traversal
    int ct = flat % (NC / 8);                // 96 channel-tiles of 8 warps
    int ib = flat / (NC / 8);                // img*NB + b
    int b = ib % NB;
    const float* src = (ib >= NB) ? in1 : in0;

    if (threadIdx.x < NN / 4) {
        ((uint32_t*)slab)[threadIdx.x] =
            ((const uint32_t*)(g_label + ib * NN))[threadIdx.x];
    }
    __syncthreads();

    int w = threadIdx.x >> 5;
    int lane = threadIdx.x & 31;
    int c = ct * 8 + w;
    const float* row = src + ((size_t)b * NC + c) * NN;

    float s0 = 0.f, s1 = 0.f, s2 = 0.f;
#pragma unroll
    for (int k = 0; k < NN / 32; ++k) {      // 18 iters
        int n = lane + 32 * k;
        float v = row[n];
        int lab = slab[n];
        s0 += (lab == 0) ? v : 0.f;
        s1 += (lab == 1) ? v : 0.f;
        s2 += (lab == 2) ? v : 0.f;
    }
#pragma unroll
    for (int o = 16; o; o >>= 1) {
        s0 += __shfl_down_sync(0xffffffffu, s0, o);
        s1 += __shfl_down_sync(0xffffffffu, s1, o);
        s2 += __shfl_down_sync(0xffffffffu, s2, o);
    }
    if (lane == 0) {
        float* dst = g_gsum + (size_t)ib * NG * NC + c;
        dst[0]      = s0;
        dst[NC]     = s1;
        dst[2 * NC] = s2;
    }
}

// ---------------------------------------------------------------------------
// Kernel D: per b, L2-normalize both 2304-dim descriptors and accumulate
// sum of squared differences. (Group means vs sums: 1/192 cancels in norm.)
// ---------------------------------------------------------------------------
__global__ void mse_kernel() {
    __shared__ float red[256];
    __shared__ float inv1s, inv2s;
    int b = blockIdx.x;
    int tid = threadIdx.x;
    const float* v1 = g_gsum + (size_t)b * NG * NC;            // image 1
    const float* v2 = g_gsum + (size_t)(NB + b) * NG * NC;     // image 2

    float ss1 = 0.f, ss2 = 0.f;
    for (int i = tid; i < NG * NC; i += 256) {
        float a = v1[i], c = v2[i];
        ss1 += a * a;
        ss2 += c * c;
    }
    red[tid] = ss1;
    __syncthreads();
    for (int o = 128; o; o >>= 1) {
        if (tid < o) red[tid] += red[tid + o];
        __syncthreads();
    }
    if (tid == 0) inv1s = 1.0f / fmaxf(sqrtf(red[0]), 1e-12f);
    __syncthreads();
    red[tid] = ss2;
    __syncthreads();
    for (int o = 128; o; o >>= 1) {
        if (tid < o) red[tid] += red[tid + o];
        __syncthreads();
    }
    if (tid == 0) inv2s = 1.0f / fmaxf(sqrtf(red[0]), 1e-12f);
    __syncthreads();

    float i1 = inv1s, i2 = inv2s;
    float acc = 0.f;
    for (int i = tid; i < NG * NC; i += 256) {
        float d = v1[i] * i1 - v2[i] * i2;
        acc += d * d;
    }
    red[tid] = acc;
    __syncthreads();
    for (int o = 128; o; o >>= 1) {
        if (tid < o) red[tid] += red[tid + o];
        __syncthreads();
    }
    if (tid == 0) g_partial[b] = red[0];
}

// ---------------------------------------------------------------------------
// Kernel E: final mean over all B * 2304 elements -> scalar output.
// ---------------------------------------------------------------------------
__global__ void final_kernel(float* __restrict__ out) {
    __shared__ float red[64];
    int tid = threadIdx.x;
    red[tid] = g_partial[tid];
    __syncthreads();
    for (int o = 32; o; o >>= 1) {
        if (tid < o) red[tid] += red[tid + o];
        __syncthreads();
    }
    if (tid == 0) out[0] = red[0] / (float)(NB * NG * NC);
}

extern "C" void kernel_launch(void* const* d_in, const int* in_sizes, int n_in,
                              void* d_out, int out_size) {
    const float* in0 = (const float*)d_in[0];
    const float* in1 = (const float*)d_in[1];
    float* out = (float*)d_out;
    (void)in_sizes; (void)n_in; (void)out_size;

    heat_kernel <<<(NIMG * NB * NN) / 256, 256>>>(in0, in1);
    label_kernel<<<NIMG * NB, NN>>>();
    gsum_kernel <<<NIMG * NB * (NC / 8), 256>>>(in0, in1);
    mse_kernel  <<<NB, 256>>>();
    final_kernel<<<1, 64>>>(out);
}

// round 3
// speedup vs baseline: 1.2516x; 1.2516x over previous
#include <cuda_runtime.h>
#include <stdint.h>

#define NB 64
#define NC 768
#define NN 576
#define NG 3
#define GS 192

// Scratch (device globals — no allocation allowed)
__device__ float g_gsum[2 * NB * NG * NC];   // [img*NB][3][NC] group sums
__device__ float g_partial[NB];              // per-b SSD
__device__ int   g_counter;                  // epilogue last-block counter

// ---------------------------------------------------------------------------
// Fused kernel: one CTA per (img,b).
//   Phase 1: heat[n] = sum_c v[c][n]        (warp-per-channel, float2 rows)
//   Rank:    stable descending rank via unique 64-bit keys, register compares
//   Phase 2: masked group sums, channels traversed in REVERSE for L2 reuse
// ---------------------------------------------------------------------------
__global__ __launch_bounds__(512, 1)
void fused_kernel(const float* __restrict__ in0, const float* __restrict__ in1) {
    __shared__ float              heat[NN];
    __shared__ unsigned long long keys[NN];
    __shared__ unsigned char      slab[NN];

    const int ib = blockIdx.x;                 // img*NB + b
    const int b  = ib & (NB - 1);
    const float* src = ((ib >= NB) ? in1 : in0) + (size_t)b * NC * NN;

    const int tid  = threadIdx.x;
    const int w    = tid >> 5;                 // 0..15
    const int lane = tid & 31;

    if (ib == 0 && tid == 0) g_counter = 0;    // reset epilogue counter

    for (int i = tid; i < NN; i += 512) heat[i] = 0.f;   // FULL 576 entries
    __syncthreads();

    // ---- Phase 1: warp w sums channels c = w + 16k into per-lane partials
    float2 acc[9];
#pragma unroll
    for (int j = 0; j < 9; ++j) acc[j] = make_float2(0.f, 0.f);

#pragma unroll 2
    for (int k = 0; k < NC / 16; ++k) {
        const float2* row = (const float2*)(src + (size_t)(w + 16 * k) * NN);
#pragma unroll
        for (int j = 0; j < 9; ++j) {
            float2 v = row[lane + 32 * j];
            acc[j].x += v.x;
            acc[j].y += v.y;
        }
    }
#pragma unroll
    for (int j = 0; j < 9; ++j) {
        int n = 2 * (lane + 32 * j);
        atomicAdd(&heat[n],     acc[j].x);
        atomicAdd(&heat[n + 1], acc[j].y);
    }
    __syncthreads();

    // ---- Build unique sort keys: (ordered-uint heat) << 10 | (1023 - n)
    // Bigger key == earlier in descending stable argsort. FULL 576 entries.
    for (int i = tid; i < NN; i += 512) {
        unsigned u = __float_as_uint(heat[i]);
        u = (u & 0x80000000u) ? ~u : (u | 0x80000000u);
        keys[i] = ((unsigned long long)u << 10) | (unsigned)(1023 - i);
    }
    __syncthreads();

    // ---- Rank + label: warp w owns n in [36w, 36w+36)
    {
        unsigned long long kr[18];
#pragma unroll
        for (int j = 0; j < 18; ++j) kr[j] = keys[lane + 32 * j];
#pragma unroll
        for (int i = 0; i < 36; ++i) {
            int n = 36 * w + i;
            unsigned long long kn = keys[n];
            unsigned cnt = 0;
#pragma unroll
            for (int j = 0; j < 18; ++j) cnt += (kr[j] > kn);
            unsigned r = __reduce_add_sync(0xffffffffu, cnt);
            if (lane == 0) slab[n] = (unsigned char)(r / GS);
        }
    }
    __syncthreads();

    // ---- Phase 2: per-lane label masks (fixed n positions per lane)
    float m0[18], m1[18];
#pragma unroll
    for (int j = 0; j < 9; ++j) {
        int n = 2 * (lane + 32 * j);
        unsigned char l0 = slab[n], l1 = slab[n + 1];
        m0[2 * j]     = (l0 == 0) ? 1.f : 0.f;
        m1[2 * j]     = (l0 == 1) ? 1.f : 0.f;
        m0[2 * j + 1] = (l1 == 0) ? 1.f : 0.f;
        m1[2 * j + 1] = (l1 == 1) ? 1.f : 0.f;
    }

    float* dst = g_gsum + (size_t)ib * NG * NC;
    for (int k = 0; k < NC / 16; ++k) {
        int c = (NC - 1) - (w + 16 * k);       // reverse traversal: L2 hits first
        const float2* row = (const float2*)(src + (size_t)c * NN);
        float tot = 0.f, s0 = 0.f, s1 = 0.f;
#pragma unroll
        for (int j = 0; j < 9; ++j) {
            float2 v = row[lane + 32 * j];
            tot += v.x + v.y;
            s0 = fmaf(v.x, m0[2 * j], fmaf(v.y, m0[2 * j + 1], s0));
            s1 = fmaf(v.x, m1[2 * j], fmaf(v.y, m1[2 * j + 1], s1));
        }
#pragma unroll
        for (int o = 16; o; o >>= 1) {
            tot += __shfl_down_sync(0xffffffffu, tot, o);
            s0  += __shfl_down_sync(0xffffffffu, s0, o);
            s1  += __shfl_down_sync(0xffffffffu, s1, o);
        }
        if (lane == 0) {
            dst[c]          = s0;
            dst[NC + c]     = s1;
            dst[2 * NC + c] = tot - s0 - s1;   // group means: 1/192 cancels in L2 norm
        }
    }
}

// ---------------------------------------------------------------------------
// Epilogue: per-b L2-normalize both descriptors, SSD, last block finalizes.
// ---------------------------------------------------------------------------
__device__ __forceinline__ float block_reduce(float v, float* sm) {
#pragma unroll
    for (int o = 16; o; o >>= 1) v += __shfl_down_sync(0xffffffffu, v, o);
    if ((threadIdx.x & 31) == 0) sm[threadIdx.x >> 5] = v;
    __syncthreads();
    if (threadIdx.x < 8) {
        v = sm[threadIdx.x];
#pragma unroll
        for (int o = 4; o; o >>= 1) v += __shfl_down_sync(0x000000ffu, v, o);
        if (threadIdx.x == 0) sm[0] = v;
    }
    __syncthreads();
    float r = sm[0];
    __syncthreads();
    return r;
}

__global__ __launch_bounds__(256, 1)
void epilogue_kernel(float* __restrict__ out) {
    __shared__ float sm[8];
    __shared__ int   is_last;
    const int b = blockIdx.x, tid = threadIdx.x;
    const float* v1 = g_gsum + (size_t)b * NG * NC;
    const float* v2 = g_gsum + (size_t)(NB + b) * NG * NC;

    float a[9], c[9];
#pragma unroll
    for (int k = 0; k < 9; ++k) { a[k] = v1[tid + 256 * k]; c[k] = v2[tid + 256 * k]; }

    float ss1 = 0.f, ss2 = 0.f;
#pragma unroll
    for (int k = 0; k < 9; ++k) { ss1 = fmaf(a[k], a[k], ss1); ss2 = fmaf(c[k], c[k], ss2); }
    ss1 = block_reduce(ss1, sm);
    ss2 = block_reduce(ss2, sm);
    float i1 = 1.f / fmaxf(sqrtf(ss1), 1e-12f);
    float i2 = 1.f / fmaxf(sqrtf(ss2), 1e-12f);

    float acc = 0.f;
#pragma unroll
    for (int k = 0; k < 9; ++k) {
        float d = a[k] * i1 - c[k] * i2;
        acc = fmaf(d, d, acc);
    }
    acc = block_reduce(acc, sm);

    if (tid == 0) {
        g_partial[b] = acc;
        __threadfence();
        int prev = atomicAdd(&g_counter, 1);
        is_last = (prev == NB - 1);
    }
    __syncthreads();

    if (is_last && tid < 32) {
        float v = g_partial[tid] + g_partial[tid + 32];
#pragma unroll
        for (int o = 16; o; o >>= 1) v += __shfl_down_sync(0xffffffffu, v, o);
        if (tid == 0) out[0] = v * (1.f / (float)(NB * NG * NC));
    }
}

extern "C" void kernel_launch(void* const* d_in, const int* in_sizes, int n_in,
                              void* d_out, int out_size) {
    const float* in0 = (const float*)d_in[0];
    const float* in1 = (const float*)d_in[1];
    float* out = (float*)d_out;
    (void)in_sizes; (void)n_in; (void)out_size;

    fused_kernel   <<<2 * NB, 512>>>(in0, in1);
    epilogue_kernel<<<NB, 256>>>(out);
}